// round 1
// baseline (speedup 1.0000x reference)
#include <cuda_runtime.h>

#define S_TOT 4096
#define A_TOT 1024
#define D_IN  5
#define H     64
#define TS    256

// Scratch for coalesced [A,S] writes, transposed to [S,A] in a second kernel.
// (16 MB static __device__ array: allowed; no allocation APIs.)
__device__ float d_scratch[(size_t)A_TOT * S_TOT];

// Accurate-enough tanh: 2 MUFU (EX2 + RCP) + a few FMA-pipe ops.
// Error ~1e-7 except ~6e-8 absolute near 0 (cancellation) -> harmless.
__device__ __forceinline__ float fast_tanh(float x) {
    float z = __expf(2.0f * x);                  // inf for large x -> handled below
    return 1.0f - __fdividef(2.0f, z + 1.0f);    // x>>0: 1-0=1 ; x<<0: 1-2=-1
}

__global__ __launch_bounds__(TS, 1) void mlp_kernel(
    const float* __restrict__ g,  const float* __restrict__ W1, const float* __restrict__ b1,
    const float* __restrict__ W2, const float* __restrict__ b2,
    const float* __restrict__ W3, const float* __restrict__ b3)
{
    __shared__ float sW1[D_IN * H];   // [d][j]
    __shared__ float sW2[H * H];      // [k][j] -- broadcast reads, conflict-free
    __shared__ float sW3[H];
    __shared__ float sB1[H];
    __shared__ float sB2[H];
    __shared__ float sB3;

    const int a   = blockIdx.y;
    const int tid = threadIdx.x;
    const int s   = blockIdx.x * TS + tid;

    // ---- stage per-atom weights in smem (coalesced gmem reads) ----
    {
        const float4* src = (const float4*)(W2 + (size_t)a * H * H);
        float4* dst = (float4*)sW2;
        #pragma unroll
        for (int i = 0; i < (H * H / 4) / TS; i++)          // 1024 float4 / 256 thr = 4
            dst[tid + i * TS] = src[tid + i * TS];
        const float* w1src = W1 + (size_t)a * D_IN * H;
        if (tid < D_IN * H) sW1[tid] = w1src[tid];          // 320 < 256? no:
        if (tid + TS < D_IN * H) sW1[tid + TS] = w1src[tid + TS];
        if (tid < H) {
            sW3[tid] = W3[(size_t)a * H + tid];
            sB1[tid] = b1[(size_t)a * H + tid];
            sB2[tid] = b2[(size_t)a * H + tid];
        }
        if (tid == 0) sB3 = b3[a];
    }

    // ---- load this thread's descriptor vector g[s, a, 0..4] ----
    float gd[D_IN];
    {
        const float* gp = g + ((size_t)s * A_TOT + a) * D_IN;
        #pragma unroll
        for (int d = 0; d < D_IN; d++) gd[d] = __ldg(gp + d);
    }

    __syncthreads();

    // ---- layer 1: h1[j] = tanh(b1[j] + sum_d g[d] * W1[d][j]) ----
    float h1[H];
    #pragma unroll
    for (int j = 0; j < H; j++) {
        float acc = sB1[j];
        #pragma unroll
        for (int d = 0; d < D_IN; d++)
            acc = fmaf(gd[d], sW1[d * H + j], acc);
        h1[j] = fast_tanh(acc);
    }

    // ---- layer 2 + layer 3 fused, output chunks of 32 to cap registers ----
    float e = sB3;
    #pragma unroll
    for (int c = 0; c < H; c += 32) {
        float acc[32];
        #pragma unroll
        for (int j = 0; j < 32; j++) acc[j] = sB2[c + j];
        #pragma unroll
        for (int k = 0; k < H; k++) {        // full unroll: h1[k] stays in regs
            const float hk = h1[k];
            #pragma unroll
            for (int j = 0; j < 32; j++)
                acc[j] = fmaf(hk, sW2[k * H + c + j], acc[j]);
        }
        #pragma unroll
        for (int j = 0; j < 32; j++)
            e = fmaf(fast_tanh(acc[j]), sW3[c + j], e);
    }

    // coalesced write in [A, S] order
    d_scratch[(size_t)a * S_TOT + s] = e;
}

// [A,S] -> [S,A] tiled transpose, fully coalesced both sides.
__global__ __launch_bounds__(256) void transpose_kernel(float* __restrict__ out)
{
    __shared__ float tile[32][33];
    const int aB = blockIdx.y * 32;
    const int sB = blockIdx.x * 32;
    const int tx = threadIdx.x;      // 32
    const int ty = threadIdx.y;      // 8
    #pragma unroll
    for (int i = 0; i < 32; i += 8)
        tile[ty + i][tx] = d_scratch[(size_t)(aB + ty + i) * S_TOT + sB + tx];
    __syncthreads();
    #pragma unroll
    for (int i = 0; i < 32; i += 8)
        out[(size_t)(sB + ty + i) * A_TOT + aB + tx] = tile[tx][ty + i];
}

extern "C" void kernel_launch(void* const* d_in, const int* in_sizes, int n_in,
                              void* d_out, int out_size)
{
    const float* g  = (const float*)d_in[0];
    const float* W1 = (const float*)d_in[1];
    const float* b1 = (const float*)d_in[2];
    const float* W2 = (const float*)d_in[3];
    const float* b2 = (const float*)d_in[4];
    const float* W3 = (const float*)d_in[5];
    const float* b3 = (const float*)d_in[6];
    float* out = (float*)d_out;

    mlp_kernel<<<dim3(S_TOT / TS, A_TOT), TS>>>(g, W1, b1, W2, b2, W3, b3);
    transpose_kernel<<<dim3(S_TOT / 32, A_TOT / 32), dim3(32, 8)>>>(out);
}

// round 4
// speedup vs baseline: 2.2899x; 2.2899x over previous
#include <cuda_runtime.h>
#include <cuda_bf16.h>
#include <cstdint>

#define S_TOT  4096
#define A_TOT  1024
#define D_IN   5
#define H      64
#define M_TILE 128
#define NTHR   128

__device__ float d_scratch[(size_t)A_TOT * S_TOT];

// ---------------- helpers ----------------
__device__ __forceinline__ uint32_t smem_u32(const void* p) {
    uint32_t a;
    asm("{ .reg .u64 t; cvta.to.shared.u64 t, %1; cvt.u32.u64 %0, t; }" : "=r"(a) : "l"(p));
    return a;
}
__device__ __forceinline__ float ex2f(float x) {
    float y; asm("ex2.approx.ftz.f32 %0, %1;" : "=f"(y) : "f"(x)); return y;
}
// Two accurate tanh sharing one reciprocal: 2x EX2 + 1x RCP (1.5 MUFU/tanh).
__device__ __forceinline__ float2 tanh2(float a, float b) {
    const float c = 2.885390081777927f;                 // 2*log2(e)
    a = fminf(9.0f, fmaxf(-9.0f, a));
    b = fminf(9.0f, fmaxf(-9.0f, b));
    float za = ex2f(a * c), zb = ex2f(b * c);
    float pa = za + 1.0f, pb = zb + 1.0f;
    float r2 = __fdividef(2.0f, pa * pb);
    return make_float2(1.0f - r2 * pb, 1.0f - r2 * pa);
}
__device__ __forceinline__ void split_pack(float x, float y, uint32_t& hi, uint32_t& lo) {
    __nv_bfloat162 h2 = __floats2bfloat162_rn(x, y);
    float hx = __bfloat162float(__low2bfloat16(h2));
    float hy = __bfloat162float(__high2bfloat16(h2));
    __nv_bfloat162 l2 = __floats2bfloat162_rn(x - hx, y - hy);
    hi = *reinterpret_cast<uint32_t*>(&h2);
    lo = *reinterpret_cast<uint32_t*>(&l2);
}
__device__ __forceinline__ void ldsm_x4(uint32_t* r, uint32_t addr) {
    asm volatile("ldmatrix.sync.aligned.m8n8.x4.shared.b16 {%0,%1,%2,%3}, [%4];"
                 : "=r"(r[0]), "=r"(r[1]), "=r"(r[2]), "=r"(r[3]) : "r"(addr));
}
__device__ __forceinline__ void ldsm_x2t(uint32_t* r, uint32_t addr) {
    asm volatile("ldmatrix.sync.aligned.m8n8.x2.trans.shared.b16 {%0,%1}, [%2];"
                 : "=r"(r[0]), "=r"(r[1]) : "r"(addr));
}
__device__ __forceinline__ void mma_bf16(float* c, const uint32_t* a, const uint32_t* b) {
    asm volatile("mma.sync.aligned.m16n8k16.row.col.f32.bf16.bf16.f32 "
                 "{%0,%1,%2,%3}, {%4,%5,%6,%7}, {%8,%9}, {%0,%1,%2,%3};"
                 : "+f"(c[0]), "+f"(c[1]), "+f"(c[2]), "+f"(c[3])
                 : "r"(a[0]), "r"(a[1]), "r"(a[2]), "r"(a[3]), "r"(b[0]), "r"(b[1]));
}

// smem: A (h1) hi/lo [128 rows][64] bf16, B (W2^T-fragged) hi/lo [64 rows k][64 n].
// All rows are 128B; 16B chunks XOR-swizzled: chunk' = chunk ^ (row & 7).
struct SmemT {
    __align__(128) __nv_bfloat16 Ahi[M_TILE * H];   // 16 KB
    __align__(128) __nv_bfloat16 Alo[M_TILE * H];   // 16 KB
    __align__(128) __nv_bfloat16 Bhi[H * H];        // 8 KB
    __align__(128) __nv_bfloat16 Blo[H * H];        // 8 KB  -> 48 KB total
};

__global__ __launch_bounds__(NTHR) void mlp_kernel(
    const float* __restrict__ g,  const float* __restrict__ W1, const float* __restrict__ b1,
    const float* __restrict__ W2, const float* __restrict__ b2,
    const float* __restrict__ W3, const float* __restrict__ b3)
{
    __shared__ SmemT sm;
    const int tid  = threadIdx.x;
    const int wid  = tid >> 5;
    const int lane = tid & 31;
    const int a    = blockIdx.y;
    const int s0   = blockIdx.x * M_TILE;

    // ---- stage B = W2[a] in natural [k][n] layout, bf16 hi/lo, swizzled ----
    {
        const float* W2a = W2 + (size_t)a * H * H;
        #pragma unroll
        for (int it = 0; it < (H * H) / NTHR; it++) {
            int i = tid + it * NTHR;
            int k = i >> 6, n = i & 63;
            float w = W2a[i];
            __nv_bfloat16 hi = __float2bfloat16(w);
            __nv_bfloat16 lo = __float2bfloat16(w - __bfloat162float(hi));
            uint32_t off = (uint32_t)k * 128 + ((((n >> 3) ^ (k & 7)) << 4) | ((n & 7) << 1));
            *(__nv_bfloat16*)((char*)sm.Bhi + off) = hi;
            *(__nv_bfloat16*)((char*)sm.Blo + off) = lo;
        }
    }

    // ---- layer 1: h1 = tanh(g . W1 + b1), split bf16 hi/lo into smem A ----
    {
        float gd[D_IN];
        const float* gp = g + ((size_t)(s0 + tid) * A_TOT + a) * D_IN;
        #pragma unroll
        for (int d = 0; d < D_IN; d++) gd[d] = __ldg(gp + d);

        const float* W1a = W1 + (size_t)a * D_IN * H;
        const float* b1a = b1 + (size_t)a * H;
        const int row = tid;
        #pragma unroll
        for (int c = 0; c < 8; c++) {                    // 8 cols per 16B chunk
            uint32_t phi[4], plo[4];
            #pragma unroll
            for (int q = 0; q < 4; q++) {
                int j = c * 8 + 2 * q;
                float2 bb = __ldg((const float2*)(b1a + j));
                float accx = bb.x, accy = bb.y;
                #pragma unroll
                for (int d = 0; d < D_IN; d++) {
                    float2 w = __ldg((const float2*)(W1a + d * H + j));
                    accx = fmaf(gd[d], w.x, accx);
                    accy = fmaf(gd[d], w.y, accy);
                }
                float2 t = tanh2(accx, accy);
                split_pack(t.x, t.y, phi[q], plo[q]);
            }
            uint32_t byte = (uint32_t)row * 128 + (((uint32_t)(c ^ (row & 7))) << 4);
            *(uint4*)((char*)sm.Ahi + byte) = make_uint4(phi[0], phi[1], phi[2], phi[3]);
            *(uint4*)((char*)sm.Alo + byte) = make_uint4(plo[0], plo[1], plo[2], plo[3]);
        }
    }
    __syncthreads();

    // ---- layer 2 on tensor cores: C = Ahi*Bhi + Ahi*Blo + Alo*Bhi ----
    float C[2][8][4];
    #pragma unroll
    for (int rt = 0; rt < 2; rt++)
        #pragma unroll
        for (int nt = 0; nt < 8; nt++)
            #pragma unroll
            for (int i = 0; i < 4; i++) C[rt][nt][i] = 0.0f;

    #pragma unroll
    for (int ks = 0; ks < 4; ks++) {
        uint32_t ahi[2][4], alo[2][4];
        #pragma unroll
        for (int rt = 0; rt < 2; rt++) {
            int arow = wid * 32 + rt * 16 + (lane & 15);
            uint32_t chunk = (uint32_t)((ks * 2 + (lane >> 4)) ^ (arow & 7));
            uint32_t ab = (uint32_t)arow * 128 + (chunk << 4);
            ldsm_x4(ahi[rt], smem_u32((char*)sm.Ahi + ab));
            ldsm_x4(alo[rt], smem_u32((char*)sm.Alo + ab));
        }
        #pragma unroll
        for (int nt = 0; nt < 8; nt++) {
            int brow = ks * 16 + (lane & 15);
            uint32_t bb = (uint32_t)brow * 128 + ((uint32_t)(nt ^ (brow & 7)) << 4);
            uint32_t bhi[2], blo[2];
            ldsm_x2t(bhi, smem_u32((char*)sm.Bhi + bb));
            ldsm_x2t(blo, smem_u32((char*)sm.Blo + bb));
            #pragma unroll
            for (int rt = 0; rt < 2; rt++) {
                mma_bf16(C[rt][nt], ahi[rt], bhi);
                mma_bf16(C[rt][nt], ahi[rt], blo);
                mma_bf16(C[rt][nt], alo[rt], bhi);
            }
        }
    }

    // ---- epilogue: +b2, tanh, dot W3, row-reduce, write scratch [A,S] ----
    {
        const float* b2a = b2 + (size_t)a * H;
        const float* w3a = W3 + (size_t)a * H;
        float e[4] = {0.f, 0.f, 0.f, 0.f};              // rows q, q+8, q+16, q+24
        const int c2 = (lane & 3) * 2;
        #pragma unroll
        for (int nt = 0; nt < 8; nt++) {
            int col = nt * 8 + c2;
            float2 bb = __ldg((const float2*)(b2a + col));
            float2 ww = __ldg((const float2*)(w3a + col));
            #pragma unroll
            for (int rt = 0; rt < 2; rt++) {
                float2 t0 = tanh2(C[rt][nt][0] + bb.x, C[rt][nt][1] + bb.y);
                float2 t1 = tanh2(C[rt][nt][2] + bb.x, C[rt][nt][3] + bb.y);
                e[rt * 2 + 0] = fmaf(t0.x, ww.x, fmaf(t0.y, ww.y, e[rt * 2 + 0]));
                e[rt * 2 + 1] = fmaf(t1.x, ww.x, fmaf(t1.y, ww.y, e[rt * 2 + 1]));
            }
        }
        #pragma unroll
        for (int i = 0; i < 4; i++) {
            e[i] += __shfl_xor_sync(0xFFFFFFFFu, e[i], 1);
            e[i] += __shfl_xor_sync(0xFFFFFFFFu, e[i], 2);
        }
        if ((lane & 3) == 0) {
            float e3 = __ldg(b3 + a);
            int q = lane >> 2;
            float* dst = d_scratch + (size_t)a * S_TOT + s0 + wid * 32;
            dst[q]      = e[0] + e3;
            dst[q + 8]  = e[1] + e3;
            dst[q + 16] = e[2] + e3;
            dst[q + 24] = e[3] + e3;
        }
    }
}

// ---------------- [A,S] -> [S,A] transpose ----------------
__global__ __launch_bounds__(256) void transpose_kernel(float* __restrict__ out)
{
    __shared__ float tile[32][33];
    const int aB = blockIdx.y * 32;
    const int sB = blockIdx.x * 32;
    const int tx = threadIdx.x;
    const int ty = threadIdx.y;
    #pragma unroll
    for (int i = 0; i < 32; i += 8)
        tile[ty + i][tx] = d_scratch[(size_t)(aB + ty + i) * S_TOT + sB + tx];
    __syncthreads();
    #pragma unroll
    for (int i = 0; i < 32; i += 8)
        out[(size_t)(sB + ty + i) * A_TOT + aB + tx] = tile[tx][ty + i];
}

extern "C" void kernel_launch(void* const* d_in, const int* in_sizes, int n_in,
                              void* d_out, int out_size)
{
    const float* g  = (const float*)d_in[0];
    const float* W1 = (const float*)d_in[1];
    const float* b1 = (const float*)d_in[2];
    const float* W2 = (const float*)d_in[3];
    const float* b2 = (const float*)d_in[4];
    const float* W3 = (const float*)d_in[5];
    const float* b3 = (const float*)d_in[6];
    float* out = (float*)d_out;

    mlp_kernel<<<dim3(S_TOT / M_TILE, A_TOT), NTHR>>>(g, W1, b1, W2, b2, W3, b3);
    transpose_kernel<<<dim3(S_TOT / 32, A_TOT / 32), dim3(32, 8)>>>(out);
}

// round 6
// speedup vs baseline: 2.3072x; 1.0075x over previous
#include <cuda_runtime.h>
#include <cuda_bf16.h>
#include <cstdint>

#define S_TOT  4096
#define A_TOT  1024
#define D_IN   5
#define H      64
#define M_TILE 128
#define NTHR   128
#define S_HALF (S_TOT / 2)

__device__ float d_scratch[(size_t)A_TOT * S_TOT];

// ---------------- helpers ----------------
__device__ __forceinline__ uint32_t smem_u32(const void* p) {
    uint32_t a;
    asm("{ .reg .u64 t; cvta.to.shared.u64 t, %1; cvt.u32.u64 %0, t; }" : "=r"(a) : "l"(p));
    return a;
}
__device__ __forceinline__ float ex2f(float x) {
    float y; asm("ex2.approx.ftz.f32 %0, %1;" : "=f"(y) : "f"(x)); return y;
}
// Two accurate tanh sharing one reciprocal: 2x EX2 + 1x RCP (1.5 MUFU/tanh).
__device__ __forceinline__ float2 tanh2(float a, float b) {
    const float c = 2.885390081777927f;                 // 2*log2(e)
    a = fminf(9.0f, fmaxf(-9.0f, a));
    b = fminf(9.0f, fmaxf(-9.0f, b));
    float za = ex2f(a * c), zb = ex2f(b * c);
    float pa = za + 1.0f, pb = zb + 1.0f;
    float r2 = __fdividef(2.0f, pa * pb);
    return make_float2(1.0f - r2 * pb, 1.0f - r2 * pa);
}
__device__ __forceinline__ void split_pack(float x, float y, uint32_t& hi, uint32_t& lo) {
    __nv_bfloat162 h2 = __floats2bfloat162_rn(x, y);
    float hx = __bfloat162float(__low2bfloat16(h2));
    float hy = __bfloat162float(__high2bfloat16(h2));
    __nv_bfloat162 l2 = __floats2bfloat162_rn(x - hx, y - hy);
    hi = *reinterpret_cast<uint32_t*>(&h2);
    lo = *reinterpret_cast<uint32_t*>(&l2);
}
__device__ __forceinline__ void ldsm_x4(uint32_t* r, uint32_t addr) {
    asm volatile("ldmatrix.sync.aligned.m8n8.x4.shared.b16 {%0,%1,%2,%3}, [%4];"
                 : "=r"(r[0]), "=r"(r[1]), "=r"(r[2]), "=r"(r[3]) : "r"(addr));
}
__device__ __forceinline__ void ldsm_x2t(uint32_t* r, uint32_t addr) {
    asm volatile("ldmatrix.sync.aligned.m8n8.x2.trans.shared.b16 {%0,%1}, [%2];"
                 : "=r"(r[0]), "=r"(r[1]) : "r"(addr));
}
__device__ __forceinline__ void mma_bf16(float* c, const uint32_t* a, const uint32_t* b) {
    asm volatile("mma.sync.aligned.m16n8k16.row.col.f32.bf16.bf16.f32 "
                 "{%0,%1,%2,%3}, {%4,%5,%6,%7}, {%8,%9}, {%0,%1,%2,%3};"
                 : "+f"(c[0]), "+f"(c[1]), "+f"(c[2]), "+f"(c[3])
                 : "r"(a[0]), "r"(a[1]), "r"(a[2]), "r"(a[3]), "r"(b[0]), "r"(b[1]));
}

// Static smem (exactly 48 KB): MMA tiles. 16B chunks XOR-swizzled: chunk' = chunk ^ (row & 7).
struct SmemT {
    __align__(128) __nv_bfloat16 Ahi[M_TILE * H];   // 16 KB
    __align__(128) __nv_bfloat16 Alo[M_TILE * H];   // 16 KB
    __align__(128) __nv_bfloat16 Bhi[H * H];        // 8 KB
    __align__(128) __nv_bfloat16 Blo[H * H];        // 8 KB
};
// Dynamic smem: per-atom small weights (513 floats).
// layout: W1[320] | b1[64] | b2[64] | w3[64] | b3[1]

__global__ __launch_bounds__(NTHR) void mlp_kernel(
    const float* __restrict__ g,  const float* __restrict__ W1, const float* __restrict__ b1,
    const float* __restrict__ W2, const float* __restrict__ b2,
    const float* __restrict__ W3, const float* __restrict__ b3, int s_base)
{
    __shared__ SmemT sm;
    extern __shared__ float dynw[];
    float* sW1 = dynw;            // [5][64]
    float* sB1 = dynw + 320;
    float* sB2 = dynw + 384;
    float* sW3 = dynw + 448;
    float* sB3 = dynw + 512;

    const int tid  = threadIdx.x;
    const int wid  = tid >> 5;
    const int lane = tid & 31;
    const int a    = blockIdx.y;
    const int s0   = s_base + blockIdx.x * M_TILE;

    // ---- stage small per-atom weights into dynamic smem (coalesced) ----
    {
        const float* w1src = W1 + (size_t)a * D_IN * H;
        #pragma unroll
        for (int i = tid; i < D_IN * H; i += NTHR) sW1[i] = w1src[i];
        if (tid < H) {
            sB1[tid] = b1[(size_t)a * H + tid];
            sB2[tid] = b2[(size_t)a * H + tid];
            sW3[tid] = W3[(size_t)a * H + tid];
        }
        if (tid == 0) sB3[0] = b3[a];
    }

    // ---- stage B = W2[a] in natural [k][n] layout, bf16 hi/lo, swizzled ----
    {
        const float* W2a = W2 + (size_t)a * H * H;
        #pragma unroll
        for (int it = 0; it < (H * H) / NTHR; it++) {
            int i = tid + it * NTHR;
            int k = i >> 6, n = i & 63;
            float w = W2a[i];
            __nv_bfloat16 hi = __float2bfloat16(w);
            __nv_bfloat16 lo = __float2bfloat16(w - __bfloat162float(hi));
            uint32_t off = (uint32_t)k * 128 + ((((n >> 3) ^ (k & 7)) << 4) | ((n & 7) << 1));
            *(__nv_bfloat16*)((char*)sm.Bhi + off) = hi;
            *(__nv_bfloat16*)((char*)sm.Blo + off) = lo;
        }
    }

    // this thread's descriptor vector (needs no barrier)
    float gd[D_IN];
    {
        const float* gp = g + ((size_t)(s0 + tid) * A_TOT + a) * D_IN;
        #pragma unroll
        for (int d = 0; d < D_IN; d++) gd[d] = __ldg(gp + d);
    }
    __syncthreads();   // dynw + B tiles ready

    // ---- layer 1: h1 = tanh(g . W1 + b1), split bf16 hi/lo into smem A ----
    {
        const int row = tid;
        #pragma unroll
        for (int c = 0; c < 8; c++) {                    // 8 cols per 16B chunk
            int j0 = c * 8;
            float4 acc0 = *(const float4*)&sB1[j0];
            float4 acc1 = *(const float4*)&sB1[j0 + 4];
            #pragma unroll
            for (int d = 0; d < D_IN; d++) {
                float4 w0 = *(const float4*)&sW1[d * H + j0];
                float4 w1 = *(const float4*)&sW1[d * H + j0 + 4];
                acc0.x = fmaf(gd[d], w0.x, acc0.x);
                acc0.y = fmaf(gd[d], w0.y, acc0.y);
                acc0.z = fmaf(gd[d], w0.z, acc0.z);
                acc0.w = fmaf(gd[d], w0.w, acc0.w);
                acc1.x = fmaf(gd[d], w1.x, acc1.x);
                acc1.y = fmaf(gd[d], w1.y, acc1.y);
                acc1.z = fmaf(gd[d], w1.z, acc1.z);
                acc1.w = fmaf(gd[d], w1.w, acc1.w);
            }
            uint32_t phi[4], plo[4];
            float2 t0 = tanh2(acc0.x, acc0.y);
            float2 t1 = tanh2(acc0.z, acc0.w);
            float2 t2 = tanh2(acc1.x, acc1.y);
            float2 t3 = tanh2(acc1.z, acc1.w);
            split_pack(t0.x, t0.y, phi[0], plo[0]);
            split_pack(t1.x, t1.y, phi[1], plo[1]);
            split_pack(t2.x, t2.y, phi[2], plo[2]);
            split_pack(t3.x, t3.y, phi[3], plo[3]);
            uint32_t byte = (uint32_t)row * 128 + (((uint32_t)(c ^ (row & 7))) << 4);
            *(uint4*)((char*)sm.Ahi + byte) = make_uint4(phi[0], phi[1], phi[2], phi[3]);
            *(uint4*)((char*)sm.Alo + byte) = make_uint4(plo[0], plo[1], plo[2], plo[3]);
        }
    }
    __syncthreads();

    // ---- layer 2 on tensor cores: C = Ahi*Bhi + Ahi*Blo + Alo*Bhi ----
    float C[2][8][4];
    #pragma unroll
    for (int rt = 0; rt < 2; rt++)
        #pragma unroll
        for (int nt = 0; nt < 8; nt++)
            #pragma unroll
            for (int i = 0; i < 4; i++) C[rt][nt][i] = 0.0f;

    #pragma unroll
    for (int ks = 0; ks < 4; ks++) {
        uint32_t ahi[2][4], alo[2][4];
        #pragma unroll
        for (int rt = 0; rt < 2; rt++) {
            int arow = wid * 32 + rt * 16 + (lane & 15);
            uint32_t chunk = (uint32_t)((ks * 2 + (lane >> 4)) ^ (arow & 7));
            uint32_t ab = (uint32_t)arow * 128 + (chunk << 4);
            ldsm_x4(ahi[rt], smem_u32((char*)sm.Ahi + ab));
            ldsm_x4(alo[rt], smem_u32((char*)sm.Alo + ab));
        }
        #pragma unroll
        for (int nt = 0; nt < 8; nt++) {
            int brow = ks * 16 + (lane & 15);
            uint32_t bb = (uint32_t)brow * 128 + ((uint32_t)(nt ^ (brow & 7)) << 4);
            uint32_t bhi[2], blo[2];
            ldsm_x2t(bhi, smem_u32((char*)sm.Bhi + bb));
            ldsm_x2t(blo, smem_u32((char*)sm.Blo + bb));
            #pragma unroll
            for (int rt = 0; rt < 2; rt++) {
                mma_bf16(C[rt][nt], ahi[rt], bhi);
                mma_bf16(C[rt][nt], ahi[rt], blo);
                mma_bf16(C[rt][nt], alo[rt], bhi);
            }
        }
    }

    // ---- epilogue: +b2, tanh, dot W3, row-reduce, write scratch [A,S] ----
    {
        float e[4] = {0.f, 0.f, 0.f, 0.f};              // rows q, q+8, q+16, q+24
        const int c2 = (lane & 3) * 2;
        #pragma unroll
        for (int nt = 0; nt < 8; nt++) {
            int col = nt * 8 + c2;
            float2 bb = *(const float2*)&sB2[col];
            float2 ww = *(const float2*)&sW3[col];
            #pragma unroll
            for (int rt = 0; rt < 2; rt++) {
                float2 t0 = tanh2(C[rt][nt][0] + bb.x, C[rt][nt][1] + bb.y);
                float2 t1 = tanh2(C[rt][nt][2] + bb.x, C[rt][nt][3] + bb.y);
                e[rt * 2 + 0] = fmaf(t0.x, ww.x, fmaf(t0.y, ww.y, e[rt * 2 + 0]));
                e[rt * 2 + 1] = fmaf(t1.x, ww.x, fmaf(t1.y, ww.y, e[rt * 2 + 1]));
            }
        }
        #pragma unroll
        for (int i = 0; i < 4; i++) {
            e[i] += __shfl_xor_sync(0xFFFFFFFFu, e[i], 1);
            e[i] += __shfl_xor_sync(0xFFFFFFFFu, e[i], 2);
        }
        if ((lane & 3) == 0) {
            float e3 = sB3[0];
            int q = lane >> 2;
            float* dst = d_scratch + (size_t)a * S_TOT + s0 + wid * 32;
            dst[q]      = e[0] + e3;
            dst[q + 8]  = e[1] + e3;
            dst[q + 16] = e[2] + e3;
            dst[q + 24] = e[3] + e3;
        }
    }
}

// ---------------- [A,S] -> [S,A] transpose (half-S per launch) ----------------
__global__ __launch_bounds__(256) void transpose_kernel(float* __restrict__ out, int s_base)
{
    __shared__ float tile[32][33];
    const int aB = blockIdx.y * 32;
    const int sB = s_base + blockIdx.x * 32;
    const int tx = threadIdx.x;
    const int ty = threadIdx.y;
    #pragma unroll
    for (int i = 0; i < 32; i += 8)
        tile[ty + i][tx] = d_scratch[(size_t)(aB + ty + i) * S_TOT + sB + tx];
    __syncthreads();
    #pragma unroll
    for (int i = 0; i < 32; i += 8)
        out[(size_t)(sB + ty + i) * A_TOT + aB + tx] = tile[tx][ty + i];
}

extern "C" void kernel_launch(void* const* d_in, const int* in_sizes, int n_in,
                              void* d_out, int out_size)
{
    const float* g  = (const float*)d_in[0];
    const float* W1 = (const float*)d_in[1];
    const float* b1 = (const float*)d_in[2];
    const float* W2 = (const float*)d_in[3];
    const float* b2 = (const float*)d_in[4];
    const float* W3 = (const float*)d_in[5];
    const float* b3 = (const float*)d_in[6];
    float* out = (float*)d_out;

    static bool attr_set = false;
    const int dyn_bytes = 513 * sizeof(float);
    if (!attr_set) {
        cudaFuncSetAttribute(mlp_kernel, cudaFuncAttributeMaxDynamicSharedMemorySize, dyn_bytes);
        attr_set = true;
    }

    // 4-launch pattern so ncu (-s 5) lands on an mlp instance, not the transpose.
    dim3 mgrid(S_HALF / M_TILE, A_TOT);
    mlp_kernel<<<mgrid, NTHR, dyn_bytes>>>(g, W1, b1, W2, b2, W3, b3, 0);
    mlp_kernel<<<mgrid, NTHR, dyn_bytes>>>(g, W1, b1, W2, b2, W3, b3, S_HALF);
    dim3 tgrid(S_HALF / 32, A_TOT / 32);
    transpose_kernel<<<tgrid, dim3(32, 8)>>>(out, 0);
    transpose_kernel<<<tgrid, dim3(32, 8)>>>(out, S_HALF);
}